// round 5
// baseline (speedup 1.0000x reference)
#include <cuda_runtime.h>
#include <math_constants.h>

#define BB 512
#define TT 1024
#define KK 48

typedef unsigned long long ull;

__device__ __forceinline__ ull pack2(float lo, float hi) {
    return ((ull)__float_as_uint(hi) << 32) | (ull)__float_as_uint(lo);
}
__device__ __forceinline__ float ulo(ull v){ return __uint_as_float((unsigned)v); }
__device__ __forceinline__ float uhi(ull v){ return __uint_as_float((unsigned)(v >> 32)); }

#define FFMA2(d,a,b,c) asm("fma.rn.f32x2 %0, %1, %2, %3;" : "=l"(d) : "l"(a), "l"(b), "l"(c))
#define FADD2(d,a,b)   asm("add.rn.f32x2 %0, %1, %2;"     : "=l"(d) : "l"(a), "l"(b))

// ---------------------------------------------------------------------------
// One block (32 threads, 1 warp) per batch. Lane j owns states j and j+32
// (j+32 >= 48 -> zero row). Forward recurrence in LINEAR space:
//   q'_j = (sum_i q_i * exp(trans[j,i])) * exp(em[t,j])        (normal step)
// with a uniform rescale r = 1/q_0 applied every 4 steps (sampled one step
// earlier via shfl so its latency hides under a full dot), and the log-scale
// C accumulated on a scalar side chain. Main loop = full 8-step groups with
// NO per-step branches; <=8-step tail carries the bound checks.
// ---------------------------------------------------------------------------
__global__ void __launch_bounds__(32) crf_fused_kernel(
    const float* __restrict__ em,
    const int*   __restrict__ tags,
    const void*  __restrict__ mask,
    const float* __restrict__ trans,
    const float* __restrict__ startt,
    const float* __restrict__ endt,
    float*       __restrict__ out)
{
    const int b  = blockIdx.x;
    const int j  = threadIdx.x;          // 0..31
    const int j2 = j + 32;
    const bool has2 = (j2 < KK);
    const int jc = has2 ? j2 : j;

    __shared__ __align__(16) float sh[2][64];

    // ---- sequence length (mask monotone prefix; dtype sniffed) ----
    const unsigned char* mb = (const unsigned char*)mask;
    int cnt = 0;
    if (mb[1] | mb[2] | mb[3]) {
        const unsigned char* m = mb + b * TT;
        #pragma unroll
        for (int t = j; t < TT; t += 32) cnt += (m[t] != 0);
    } else {
        const unsigned int* m = (const unsigned int*)mask + b * TT;
        #pragma unroll
        for (int t = j; t < TT; t += 32) cnt += (m[t] != 0u);
    }
    #pragma unroll
    for (int o = 16; o; o >>= 1) cnt += __shfl_xor_sync(0xffffffffu, cnt, o);
    const int len = cnt;

    const size_t em_base = (size_t)b * TT * KK;

    // ---- numerator score ----
    float acc = 0.0f;
    {
        const int base = b * TT;
        for (int k = 0; k * 32 < len; k++) {
            int t = k * 32 + j;
            if (t >= 1 && t < len) {
                int cur  = tags[base + t];
                int prev = tags[base + t - 1];
                acc += em[em_base + (size_t)t * KK + cur] + trans[prev * KK + cur];
            }
        }
        #pragma unroll
        for (int o = 16; o; o >>= 1) acc += __shfl_xor_sync(0xffffffffu, acc, o);
    }

    // ---- exp(transitions) rows, packed f32x2 ----
    ull eTa[24], eTb[24];
    #pragma unroll
    for (int i = 0; i < 24; i++) {
        eTa[i] = pack2(__expf(trans[j * KK + 2 * i]),
                       __expf(trans[j * KK + 2 * i + 1]));
        eTb[i] = has2 ? pack2(__expf(trans[j2 * KK + 2 * i]),
                              __expf(trans[j2 * KK + 2 * i + 1]))
                      : 0ULL;
    }
    float eend0 = __expf(endt[j]);
    float eend1 = has2 ? __expf(endt[jc]) : 0.0f;

    // ---- init t = 0 ----
    float a00 = startt[j] + em[em_base + j];
    float c0  = __shfl_sync(0xffffffffu, a00, 0);
    float q0v = __expf(a00 - c0);
    float q1v = has2 ? __expf(startt[jc] + em[em_base + jc] - c0) : 0.0f;
    sh[0][j]  = q0v;
    sh[0][j2] = q1v;
    float C = c0, r = 1.0f, xcur = 1.0f;
    __syncthreads();

    // ---- emission-exp prefetch (8 deep, double buffered) ----
    float eA0[8], eA1[8], eB0[8], eB1[8];
    #pragma unroll
    for (int s = 0; s < 8; s++) {
        int tt = 1 + s; tt = (tt < TT) ? tt : (TT - 1);
        eA0[s] = __expf(em[em_base + (size_t)tt * KK + j]);
        eA1[s] = __expf(em[em_base + (size_t)tt * KK + jc]);
    }

    // one step; RD/WR compile-time; APPLY: multiply stale rescale + C update;
    // SAMPLE: grab q_0 for the next APPLY (latency hidden by next dots)
#define STEP(RD, WR, EE0, EE1, APPLY, SAMPLE) do {                             \
    if (APPLY) r = __fdividef(1.0f, xcur);                                     \
    const double2* P2 = (const double2*)sh[RD];                                \
    ull A0=0,A1=0,A2=0,A3=0,B0=0,B1=0,B2=0,B3=0;                               \
    _Pragma("unroll")                                                          \
    for (int i = 0; i < 12; i += 2) {                                          \
        double2 qA = P2[i]; double2 qB = P2[i + 1];                            \
        ull xa=__double_as_longlong(qA.x), xb=__double_as_longlong(qA.y);      \
        ull xc=__double_as_longlong(qB.x), xd=__double_as_longlong(qB.y);      \
        FFMA2(A0, xa, eTa[2*i+0], A0);  FFMA2(A1, xb, eTa[2*i+1], A1);         \
        FFMA2(A2, xc, eTa[2*i+2], A2);  FFMA2(A3, xd, eTa[2*i+3], A3);         \
        FFMA2(B0, xa, eTb[2*i+0], B0);  FFMA2(B1, xb, eTb[2*i+1], B1);         \
        FFMA2(B2, xc, eTb[2*i+2], B2);  FFMA2(B3, xd, eTb[2*i+3], B3);         \
    }                                                                          \
    FADD2(A0, A0, A1); FADD2(A2, A2, A3); FADD2(A0, A0, A2);                   \
    FADD2(B0, B0, B1); FADD2(B2, B2, B3); FADD2(B0, B0, B2);                   \
    float u0 = ulo(A0) + uhi(A0);                                              \
    float u1 = ulo(B0) + uhi(B0);                                              \
    if (APPLY) {                                                               \
        C += __logf(xcur);                                                     \
        q0v = u0 * (EE0) * r;                                                  \
        q1v = u1 * (EE1) * r;                                                  \
    } else {                                                                   \
        q0v = u0 * (EE0);                                                      \
        q1v = u1 * (EE1);                                                      \
    }                                                                          \
    sh[WR][j]  = q0v;                                                          \
    sh[WR][j2] = q1v;                                                          \
    if (SAMPLE) xcur = __shfl_sync(0xffffffffu, q0v, 0);                       \
    __syncthreads();                                                           \
} while (0)

    // full-group body: prefetch next 8, then 8 branch-free steps.
    // roles: s0 apply, s3 sample, s4 apply, s7 sample (4-step rescale cadence)
#define GROUP(EC0, EC1, EN0, EN1) do {                                         \
    _Pragma("unroll")                                                          \
    for (int s = 0; s < 8; s++) {                                              \
        int tt = t0 + 8 + s; tt = (tt < TT) ? tt : (TT - 1);                   \
        EN0[s] = __expf(em[em_base + (size_t)tt * KK + j]);                    \
        EN1[s] = __expf(em[em_base + (size_t)tt * KK + jc]);                   \
    }                                                                          \
    STEP(0, 1, EC0[0], EC1[0], 1, 0);                                          \
    STEP(1, 0, EC0[1], EC1[1], 0, 0);                                          \
    STEP(0, 1, EC0[2], EC1[2], 0, 0);                                          \
    STEP(1, 0, EC0[3], EC1[3], 0, 1);                                          \
    STEP(0, 1, EC0[4], EC1[4], 1, 0);                                          \
    STEP(1, 0, EC0[5], EC1[5], 0, 0);                                          \
    STEP(0, 1, EC0[6], EC1[6], 0, 0);                                          \
    STEP(1, 0, EC0[7], EC1[7], 0, 1);                                          \
    t0 += 8;                                                                   \
} while (0)

    int t0 = 1;
    int useA = 1;
    // main loop: only FULL groups (t0..t0+7 all < len), no per-step checks
    while (t0 <= len - 8) {
        if (useA) GROUP(eA0, eA1, eB0, eB1);
        else      GROUP(eB0, eB1, eA0, eA1);
        useA ^= 1;
    }

    // tail: <= 8 steps (read from the buffer the last full group prefetched)
    {
        const int nrem = len - t0;      // 0..7 steps remaining (t0..len-1)
        #pragma unroll
        for (int s = 0; s < 8; s++) {
            if (s >= nrem) break;
            float E0 = useA ? eA0[s] : eB0[s];
            float E1 = useA ? eA1[s] : eB1[s];
            if (s & 1) {
                if (s == 3) STEP(1, 0, E0, E1, 0, 1);
                else if (s == 7) STEP(1, 0, E0, E1, 0, 1);
                else STEP(1, 0, E0, E1, 0, 0);
            } else {
                if (s == 0) STEP(0, 1, E0, E1, 1, 0);
                else if (s == 4) STEP(0, 1, E0, E1, 1, 0);
                else STEP(0, 1, E0, E1, 0, 0);
            }
        }
    }
#undef GROUP
#undef STEP

    // ---- out = score - (C + log( sum_j q_j * exp(end_j) )) ----
    float tot = q0v * eend0 + q1v * eend1;
    #pragma unroll
    for (int o = 16; o; o >>= 1) tot += __shfl_xor_sync(0xffffffffu, tot, o);

    if (j == 0) {
        const int base = b * TT;
        int tag0 = tags[base];
        float score = startt[tag0] + em[em_base + tag0] + acc
                    + endt[tags[base + len - 1]];
        out[b] = score - (C + __logf(tot));
    }
}

extern "C" void kernel_launch(void* const* d_in, const int* in_sizes, int n_in,
                              void* d_out, int out_size)
{
    const float* em    = (const float*)d_in[0];
    const int*   tags  = (const int*)d_in[1];
    const void*  mask  = d_in[2];
    const float* trans = (const float*)d_in[3];
    const float* stt   = (const float*)d_in[4];
    const float* ent   = (const float*)d_in[5];
    float*       out   = (float*)d_out;

    crf_fused_kernel<<<BB, 32>>>(em, tags, mask, trans, stt, ent, out);
}

// round 6
// speedup vs baseline: 1.4951x; 1.4951x over previous
#include <cuda_runtime.h>
#include <math_constants.h>

#define BB 512
#define TT 1024
#define KK 48

typedef unsigned long long ull;

__device__ __forceinline__ ull pack2(float lo, float hi) {
    return ((ull)__float_as_uint(hi) << 32) | (ull)__float_as_uint(lo);
}
__device__ __forceinline__ float ulo(ull v){ return __uint_as_float((unsigned)v); }
__device__ __forceinline__ float uhi(ull v){ return __uint_as_float((unsigned)(v >> 32)); }

#define FFMA2(d,a,b,c) asm("fma.rn.f32x2 %0, %1, %2, %3;" : "=l"(d) : "l"(a), "l"(b), "l"(c))
#define FADD2(d,a,b)   asm("add.rn.f32x2 %0, %1, %2;"     : "=l"(d) : "l"(a), "l"(b))

// ---------------------------------------------------------------------------
// One block (32 threads, 1 warp) per batch. Lane l owns states 2l and 2l+1
// (lanes 24..31: zero rows). Forward recurrence in LINEAR space:
//   q'_j = (sum_i q_i * exp(trans[j,i])) * exp(em[t,j]) / q_0(prev)
// with the uniform rescale one step stale (cancels algebraically) and the
// log-scale C on a scalar side chain. Emissions go through a 3-stage
// pipeline: LDG (group g+1) | exp of raw loaded last group | consume —
// so no MUFU ever waits on an in-flight load.
// ---------------------------------------------------------------------------
__global__ void __launch_bounds__(32) crf_fused_kernel(
    const float* __restrict__ em,
    const int*   __restrict__ tags,
    const void*  __restrict__ mask,
    const float* __restrict__ trans,
    const float* __restrict__ startt,
    const float* __restrict__ endt,
    float*       __restrict__ out)
{
    const int b  = blockIdx.x;
    const int l  = threadIdx.x;            // 0..31
    const int s0 = 2 * l, s1 = 2 * l + 1;
    const bool valid = (s0 < KK);          // l < 24
    const int e0 = valid ? s0 : (KK - 2);  // clamped pair base (8B aligned)

    __shared__ __align__(16) float sh[2][64];

    // ---- sequence length (mask monotone prefix; dtype sniffed:
    //      mask[0,1] guaranteed true since lengths >= T/2) ----
    const unsigned char* mb = (const unsigned char*)mask;
    int cnt = 0;
    if (mb[1] | mb[2] | mb[3]) {
        const unsigned char* m = mb + b * TT;
        #pragma unroll
        for (int t = l; t < TT; t += 32) cnt += (m[t] != 0);
    } else {
        const unsigned int* m = (const unsigned int*)mask + b * TT;
        #pragma unroll
        for (int t = l; t < TT; t += 32) cnt += (m[t] != 0u);
    }
    #pragma unroll
    for (int o = 16; o; o >>= 1) cnt += __shfl_xor_sync(0xffffffffu, cnt, o);
    const int len = cnt;

    const size_t em_base = (size_t)b * TT * KK;

    // ---- numerator score ----
    float acc = 0.0f;
    {
        const int base = b * TT;
        for (int k = 0; k * 32 < len; k++) {
            int t = k * 32 + l;
            if (t >= 1 && t < len) {
                int cur  = tags[base + t];
                int prev = tags[base + t - 1];
                acc += em[em_base + (size_t)t * KK + cur] + trans[prev * KK + cur];
            }
        }
        #pragma unroll
        for (int o = 16; o; o >>= 1) acc += __shfl_xor_sync(0xffffffffu, acc, o);
    }

    // ---- exp(transitions) rows for both owned states (packed f32x2) ----
    ull eTa[24], eTb[24];
    #pragma unroll
    for (int i = 0; i < 24; i++) {
        eTa[i] = valid ? pack2(__expf(trans[s0 * KK + 2 * i]),
                               __expf(trans[s0 * KK + 2 * i + 1])) : 0ULL;
        eTb[i] = valid ? pack2(__expf(trans[s1 * KK + 2 * i]),
                               __expf(trans[s1 * KK + 2 * i + 1])) : 0ULL;
    }
    float eend0 = valid ? __expf(endt[s0]) : 0.0f;
    float eend1 = valid ? __expf(endt[s1]) : 0.0f;

    // ---- init t = 0 ----
    float a0 = valid ? (startt[s0] + em[em_base + s0]) : 0.0f;
    float a1 = valid ? (startt[s1] + em[em_base + s1]) : 0.0f;
    float c0 = __shfl_sync(0xffffffffu, a0, 0);
    float q0v = valid ? __expf(a0 - c0) : 0.0f;   // lane0.x == 1 exactly
    float q1v = valid ? __expf(a1 - c0) : 0.0f;
    ((float2*)sh[0])[l] = make_float2(q0v, q1v);
    float C = c0, r = 1.0f, xcur = 1.0f;
    __syncthreads();

    // ---- emission pipeline: prime ----
    float2 EA[8], EB[8], R[8];
    #pragma unroll
    for (int s = 0; s < 8; s++) {               // exp for t = 1..8 (exposed once)
        int tt = 1 + s; tt = (tt < TT) ? tt : (TT - 1);
        float2 v = *(const float2*)&em[em_base + (size_t)tt * KK + e0];
        EA[s] = make_float2(__expf(v.x), __expf(v.y));
    }
    #pragma unroll
    for (int s = 0; s < 8; s++) {               // raw for t = 9..16
        int tt = 9 + s; tt = (tt < TT) ? tt : (TT - 1);
        R[s] = *(const float2*)&em[em_base + (size_t)tt * KK + e0];
    }

#define STEP(RD, WR, EE) do {                                                  \
    const double2* P2 = (const double2*)sh[RD];                                \
    ull A0=0,A1=0,A2=0,A3=0,B0=0,B1=0,B2=0,B3=0;                               \
    _Pragma("unroll")                                                          \
    for (int i = 0; i < 12; i += 2) {                                          \
        double2 qA = P2[i]; double2 qB = P2[i + 1];                            \
        ull xa=__double_as_longlong(qA.x), xb=__double_as_longlong(qA.y);      \
        ull xc=__double_as_longlong(qB.x), xd=__double_as_longlong(qB.y);      \
        FFMA2(A0, xa, eTa[2*i+0], A0);  FFMA2(A1, xb, eTa[2*i+1], A1);         \
        FFMA2(A2, xc, eTa[2*i+2], A2);  FFMA2(A3, xd, eTa[2*i+3], A3);         \
        FFMA2(B0, xa, eTb[2*i+0], B0);  FFMA2(B1, xb, eTb[2*i+1], B1);         \
        FFMA2(B2, xc, eTb[2*i+2], B2);  FFMA2(B3, xd, eTb[2*i+3], B3);         \
    }                                                                          \
    FADD2(A0, A0, A1); FADD2(A2, A2, A3); FADD2(A0, A0, A2);                   \
    FADD2(B0, B0, B1); FADD2(B2, B2, B3); FADD2(B0, B0, B2);                   \
    float u0 = ulo(A0) + uhi(A0);                                              \
    float u1 = ulo(B0) + uhi(B0);                                              \
    C += __logf(xcur);                /* scalar side chain */                  \
    q0v = u0 * (EE).x * r;                                                     \
    q1v = u1 * (EE).y * r;                                                     \
    ((float2*)sh[WR])[l] = make_float2(q0v, q1v);                              \
    xcur = __shfl_sync(0xffffffffu, q0v, 0);                                   \
    __syncthreads();                  /* nw=1 barrier */                       \
    r = __fdividef(1.0f, xcur);       /* stale rescale, off-chain */           \
} while (0)

    // group: ECUR consumed now; ENXT = exp(R) (loads from last group, landed);
    // R refilled for the group after next. t0 stays odd -> RD = s&1.
#define GROUP(ECUR, ENXT) do {                                                 \
    _Pragma("unroll")                                                          \
    for (int s = 0; s < 8; s++)                                                \
        ENXT[s] = make_float2(__expf(R[s].x), __expf(R[s].y));                 \
    _Pragma("unroll")                                                          \
    for (int s = 0; s < 8; s++) {                                              \
        int tt = t0 + 16 + s; tt = (tt < TT) ? tt : (TT - 1);                  \
        R[s] = *(const float2*)&em[em_base + (size_t)tt * KK + e0];            \
    }                                                                          \
    {                                                                          \
        const int tend = (t0 + 8 < len) ? (t0 + 8) : len;                      \
        _Pragma("unroll")                                                      \
        for (int s = 0; s < 8; s++) {                                          \
            if (t0 + s >= tend) break;                                         \
            if (s & 1) STEP(1, 0, ECUR[s]);                                    \
            else       STEP(0, 1, ECUR[s]);                                    \
        }                                                                      \
    }                                                                          \
    t0 += 8;                                                                   \
} while (0)

    int t0 = 1;
    while (t0 < len) {
        GROUP(EA, EB);
        if (t0 >= len) break;
        GROUP(EB, EA);
    }
#undef GROUP
#undef STEP

    // ---- out = score - (C + log( sum_j q_j * exp(end_j) )) ----
    float tot = q0v * eend0 + q1v * eend1;
    #pragma unroll
    for (int o = 16; o; o >>= 1) tot += __shfl_xor_sync(0xffffffffu, tot, o);

    if (l == 0) {
        const int base = b * TT;
        int tag0 = tags[base];
        float score = startt[tag0] + em[em_base + tag0] + acc
                    + endt[tags[base + len - 1]];
        out[b] = score - (C + __logf(tot));
    }
}

extern "C" void kernel_launch(void* const* d_in, const int* in_sizes, int n_in,
                              void* d_out, int out_size)
{
    const float* em    = (const float*)d_in[0];
    const int*   tags  = (const int*)d_in[1];
    const void*  mask  = d_in[2];
    const float* trans = (const float*)d_in[3];
    const float* stt   = (const float*)d_in[4];
    const float* ent   = (const float*)d_in[5];
    float*       out   = (float*)d_out;

    crf_fused_kernel<<<BB, 32>>>(em, tags, mask, trans, stt, ent, out);
}